// round 16
// baseline (speedup 1.0000x reference)
#include <cuda_runtime.h>
#include <cuda_fp16.h>

typedef unsigned int u32;

#define B_    512
#define ROWS  65536   // B_*128

// ---------------------------------------------------------------------------
// Device-global scratch (allocation-free rule)
// HL block = 16KB: [hi: 128 row x 32 k][lo: 128 row x 32 k], swizzled:
//   byte_in_half_block = row*64 + ((col*2) ^ (((row>>1)&3)<<4))
// g_A  : [b][kc:4]  HL blocks
// g_C  : [rt][kc:16] HL blocks
// g_Xt/g_Ht : [b][kc:4][256 feat][32 tok] fp16 blocks (8KB)
// g_Wz/g_Wr : [nb:2][kc:16][128 n][32 k] 8KB blocks
// g_Wh1/g_Wh2 : [nb:2][kc:8][128 n][32 k] 8KB blocks
// g_Z/g_R  : BLOCKED [(rt*2+nb)][128 row][128 col] fp32, XOR-swizzled:
//   byte_in_row = (cl*4) ^ ((lr&3)<<5)
// ---------------------------------------------------------------------------
__device__ __align__(128) __half g_A[(size_t)B_ * 4 * 8192];
__device__ __align__(128) __half g_Xt[(size_t)B_ * 256 * 128];
__device__ __align__(128) __half g_Ht[(size_t)B_ * 256 * 128];
__device__ __align__(128) __half g_C[(size_t)ROWS * 1024];      // 134MB (hi+lo)
__device__ __align__(128) float  g_Z[(size_t)ROWS * 256];
__device__ __align__(128) float  g_R[(size_t)ROWS * 256];
__device__ __align__(128) __half g_Wz[256 * 512];
__device__ __align__(128) __half g_Wr[256 * 512];
__device__ __align__(128) __half g_Wh1[256 * 256];
__device__ __align__(128) __half g_Wh2[256 * 256];

// ---------------------------------------------------------------------------
// Helpers
// ---------------------------------------------------------------------------
__device__ __forceinline__ u32 smem_u32(const void* p) {
    u32 a;
    asm("{ .reg .u64 t; cvta.to.shared.u64 t, %1; cvt.u32.u64 %0, t; }" : "=r"(a) : "l"(p));
    return a;
}
__device__ __forceinline__ void ldsm4(u32* r, u32 addr) {
    asm volatile("ldmatrix.sync.aligned.m8n8.x4.shared.b16 {%0,%1,%2,%3}, [%4];"
                 : "=r"(r[0]), "=r"(r[1]), "=r"(r[2]), "=r"(r[3]) : "r"(addr));
}
__device__ __forceinline__ void mma16816(float* d, const u32* a, const u32* b) {
    asm volatile(
        "mma.sync.aligned.m16n8k16.row.col.f32.f16.f16.f32 "
        "{%0,%1,%2,%3}, {%4,%5,%6,%7}, {%8,%9}, {%0,%1,%2,%3};"
        : "+f"(d[0]), "+f"(d[1]), "+f"(d[2]), "+f"(d[3])
        : "r"(a[0]), "r"(a[1]), "r"(a[2]), "r"(a[3]), "r"(b[0]), "r"(b[1]));
}
__device__ __forceinline__ float sigmoidf_fast(float x) {
    return 1.0f / (1.0f + __expf(-x));
}
__device__ __forceinline__ void split2(float x, __half& h, __half& l) {
    h = __float2half_rn(x);
    l = __float2half_rn(x - __half2float(h));
}
// ---- bulk DMA + mbarrier ----
__device__ __forceinline__ void cp_bulk(u32 sdst, const void* gsrc, u32 bytes, u32 mbar) {
    asm volatile(
        "{ .reg .u64 p; cvta.to.global.u64 p, %1;\n\t"
        "cp.async.bulk.shared::cluster.global.mbarrier::complete_tx::bytes [%0], [p], %2, [%3]; }"
        :: "r"(sdst), "l"(gsrc), "r"(bytes), "r"(mbar) : "memory");
}
__device__ __forceinline__ void cp_bulk_store(void* gdst, u32 ssrc, u32 bytes) {
    asm volatile(
        "{ .reg .u64 p; cvta.to.global.u64 p, %0;\n\t"
        "cp.async.bulk.global.shared::cta.bulk_group [p], [%1], %2; }"
        :: "l"(gdst), "r"(ssrc), "r"(bytes) : "memory");
}
__device__ __forceinline__ void bulk_store_commit() {
    asm volatile("cp.async.bulk.commit_group;" ::: "memory");
}
__device__ __forceinline__ void bulk_store_wait0() {
    asm volatile("cp.async.bulk.wait_group 0;" ::: "memory");
}
__device__ __forceinline__ void fence_async_shared() {
    asm volatile("fence.proxy.async.shared::cta;" ::: "memory");
}
__device__ __forceinline__ void mbar_init(u32 addr, u32 cnt) {
    asm volatile("mbarrier.init.shared.b64 [%0], %1;" :: "r"(addr), "r"(cnt) : "memory");
}
__device__ __forceinline__ void mbar_expect(u32 addr, u32 bytes) {
    asm volatile("mbarrier.arrive.expect_tx.shared::cta.b64 _, [%0], %1;"
                 :: "r"(addr), "r"(bytes) : "memory");
}
__device__ __forceinline__ void mbar_wait(u32 addr, u32 parity) {
    asm volatile(
        "{\n\t.reg .pred P;\n\t"
        "WAIT_%=:\n\t"
        "mbarrier.try_wait.parity.acquire.cta.shared::cta.b64 P, [%0], %1, 0x989680;\n\t"
        "@!P bra.uni WAIT_%=;\n\t}"
        :: "r"(addr), "r"(parity) : "memory");
}

#define ZERO_ACC(acc, NI) \
    _Pragma("unroll") for (int _a = 0; _a < 2; _a++) \
    _Pragma("unroll") for (int _c = 0; _c < NI; _c++) \
    _Pragma("unroll") for (int _d = 0; _d < 4; _d++) acc[_a][_c][_d] = 0.0f;

// ---------------------------------------------------------------------------
// Conversion kernels (unchanged from R15)
// ---------------------------------------------------------------------------
__global__ __launch_bounds__(256) void conv_A(const float* __restrict__ A) {
    size_t i = ((size_t)blockIdx.x * 256 + threadIdx.x) * 4;
    float4 v = *(const float4*)(A + i);
    int b   = (int)(i >> 14);
    int rem = (int)(i & 16383);
    int row = rem >> 7, col = rem & 127;
    int kc = col >> 5, kk = col & 31;
    __half h0, h1, h2, h3, l0, l1, l2, l3;
    split2(v.x, h0, l0); split2(v.y, h1, l1); split2(v.z, h2, l2); split2(v.w, h3, l3);
    u32 swo = (u32)((kk * 2) ^ (((row >> 1) & 3) << 4));
    size_t hidx = (size_t)(b * 4 + kc) * 8192 + (size_t)row * 32 + (swo >> 1);
    *(__half2*)(g_A + hidx)            = __halves2half2(h0, h1);
    *(__half2*)(g_A + hidx + 2)        = __halves2half2(h2, h3);
    *(__half2*)(g_A + hidx + 4096)     = __halves2half2(l0, l1);
    *(__half2*)(g_A + hidx + 4096 + 2) = __halves2half2(l2, l3);
}

__global__ __launch_bounds__(256) void conv_XH(const float* __restrict__ X,
                                               const float* __restrict__ Hd) {
    int z = blockIdx.z;
    int b = z & (B_ - 1);
    const float* src = (z < B_) ? X : Hd;
    __half* dst = (z < B_) ? g_Xt : g_Ht;
    __shared__ float s[32][33];
    __shared__ __align__(16) char sm2[2048];
    int tx = threadIdx.x & 31, ty = threadIdx.x >> 5;
    int f0 = blockIdx.x * 32, t0 = blockIdx.y * 32;
    const float* sp = src + (size_t)b * 128 * 256;
#pragma unroll
    for (int r = 0; r < 4; r++)
        s[ty + 8 * r][tx] = sp[(size_t)(t0 + ty + 8 * r) * 256 + f0 + tx];
    __syncthreads();
#pragma unroll
    for (int r = 0; r < 4; r++) {
        int fl = ty + 8 * r;
        int tk = tx;
        u32 off = (u32)(fl * 64 + ((tk * 2) ^ (((fl >> 1) & 3) << 4)));
        *(__half*)(sm2 + off) = __float2half_rn(s[tx][fl]);
    }
    __syncthreads();
    if (threadIdx.x < 128) {
        size_t dbytes = (((size_t)(b * 4 + blockIdx.y) * 256 + f0) * 32) * 2;
        *(uint4*)((char*)dst + dbytes + threadIdx.x * 16) =
            *(const uint4*)(sm2 + threadIdx.x * 16);
    }
}

__global__ __launch_bounds__(256) void conv_W(const float* __restrict__ Wz1, const float* __restrict__ Wz2,
                                              const float* __restrict__ Wr1, const float* __restrict__ Wr2,
                                              const float* __restrict__ Wh1, const float* __restrict__ Wh2) {
    int job = blockIdx.z;
    const float* src; __half* dst; int koff, kcn;
    switch (job) {
        case 0:  src = Wz1; dst = g_Wz;  koff = 0;   kcn = 16; break;
        case 1:  src = Wz2; dst = g_Wz;  koff = 256; kcn = 16; break;
        case 2:  src = Wr1; dst = g_Wr;  koff = 0;   kcn = 16; break;
        case 3:  src = Wr2; dst = g_Wr;  koff = 256; kcn = 16; break;
        case 4:  src = Wh1; dst = g_Wh1; koff = 0;   kcn = 8;  break;
        default: src = Wh2; dst = g_Wh2; koff = 0;   kcn = 8;  break;
    }
    __shared__ float s[32][33];
    int tx = threadIdx.x & 31, ty = threadIdx.x >> 5;
    int n0 = blockIdx.x * 32, k0 = blockIdx.y * 32;
#pragma unroll
    for (int r = 0; r < 4; r++)
        s[ty + 8 * r][tx] = src[(size_t)(k0 + ty + 8 * r) * 256 + n0 + tx];
    __syncthreads();
#pragma unroll
    for (int r = 0; r < 4; r++) {
        int n = n0 + ty + 8 * r;
        int k = koff + k0 + tx;
        int nb = n >> 7, nr = n & 127, kc = k >> 5, kk = k & 31;
        size_t hidx = (size_t)(nb * kcn + kc) * 4096 + nr * 32
                    + ((((kk * 2) ^ (((nr >> 1) & 3) << 4))) >> 1);
        dst[hidx] = __float2half_rn(s[tx][ty + 8 * r]);
    }
}

// ---------------------------------------------------------------------------
// Lane constants for blocked-swizzle A fragments (shared across kernels).
// ---------------------------------------------------------------------------
__device__ __forceinline__ u32 bsl_of(int lane) {
    return (u32)((lane & 7) + ((lane >> 4) << 3));
}

#define STAGE1 24576
#define MB1    98304
#define KSMEM1 (98304 + 64)
#define STAGE2 32768
#define MB2    131072
#define KSMEM2 (131072 + 64)

// Z/R blocked addressing: block (rt*2+nb), float index within block
__device__ __forceinline__ u32 zr_off(int lr, int cl) {
    return (u32)(lr * 128) + ((((u32)cl * 4) ^ (((u32)lr & 3) << 5)) >> 2);
}

// ---------------------------------------------------------------------------
// k1: unchanged (R14/R15 winner). grid (4, 512), 256 thr, 2 CTA/SM.
// ---------------------------------------------------------------------------
__global__ __launch_bounds__(256, 2) void k1() {
    extern __shared__ char sm[];
    const int tid = threadIdx.x, lane = tid & 31, wid = tid >> 5;
    const int wm = wid >> 1, wn = wid & 1;
    const int nb = blockIdx.x, b = blockIdx.y;

    const char* Ab = (const char*)g_A + (size_t)b * (4 * 16384);
    const char* Bx = (const char*)g_Xt + (size_t)b * 65536 + (size_t)nb * 4096;
    const char* Bh = (const char*)g_Ht + (size_t)b * 65536 + (size_t)nb * 4096;

    const u32 sb = smem_u32(sm);
    const u32 mb0 = sb + MB1;
    const u32 arow = (u32)(wm * 32 + (lane & 15)) * 64;
    const u32 aswp = ((((u32)lane & 15) >> 1) & 3) << 4;
    const u32 ahalf = (u32)(lane >> 4);
    const u32 bsl = bsl_of(lane);
    const u32 brow = (u32)(wn * 64 + bsl) * 64;
    const u32 bswp = ((bsl >> 1) & 3) << 4;
    const u32 bhalf = (u32)((lane >> 3) & 1);

    if (tid == 0) {
#pragma unroll
        for (int s = 0; s < 4; s++) mbar_init(mb0 + s * 8, 1);
#pragma unroll
        for (int j = 0; j < 4; j++) {
            u32 st = sb + j * STAGE1, mb = mb0 + j * 8;
            mbar_expect(mb, STAGE1);
            cp_bulk(st,                Ab + (size_t)j * 16384, 16384, mb);
            cp_bulk(st + 16384,        Bx + (size_t)j * 16384, 4096, mb);
            cp_bulk(st + 16384 + 4096, Bh + (size_t)j * 16384, 4096, mb);
        }
    }
    __syncthreads();

    float acc[2][8][4];
    ZERO_ACC(acc, 8);

    for (int ch = 0; ch < 4; ch++) {
        mbar_wait(mb0 + ch * 8, 0);
        __syncthreads();
        const u32 sA = sb + ch * STAGE1, sL = sA + 8192, sB = sA + 16384;
#pragma unroll
        for (int k16 = 0; k16 < 2; k16++) {
            const u32 goffA = (((2 * k16 + ahalf) << 4) ^ aswp);
            const u32 goffB = (((2 * k16 + bhalf) << 4) ^ bswp);
            u32 bf[4][4];
#pragma unroll
            for (int q = 0; q < 4; q++)
                ldsm4(bf[q], sB + brow + q * 1024 + goffB);
            u32 ah[2][4], al[2][4];
#pragma unroll
            for (int mi = 0; mi < 2; mi++) {
                ldsm4(ah[mi], sA + arow + mi * 1024 + goffA);
                ldsm4(al[mi], sL + arow + mi * 1024 + goffA);
            }
#pragma unroll
            for (int mi = 0; mi < 2; mi++)
#pragma unroll
                for (int ni = 0; ni < 8; ni++)
                    mma16816(acc[mi][ni], ah[mi], &bf[ni >> 1][(ni & 1) * 2]);
#pragma unroll
            for (int mi = 0; mi < 2; mi++)
#pragma unroll
                for (int ni = 0; ni < 8; ni++)
                    mma16816(acc[mi][ni], al[mi], &bf[ni >> 1][(ni & 1) * 2]);
        }
    }

    __syncthreads();
#pragma unroll
    for (int mi = 0; mi < 2; mi++)
#pragma unroll
        for (int ni = 0; ni < 8; ni++)
#pragma unroll
            for (int hh = 0; hh < 2; hh++) {
                int lr = wm * 32 + mi * 16 + (lane >> 2) + hh * 8;
                int cl = wn * 64 + ni * 8 + (lane & 3) * 2;
                int blk = cl >> 5, cc = cl & 31;
                u32 swo = (u32)((cc * 2) ^ (((lr >> 1) & 3) << 4));
                u32 saddr = sb + blk * 16384 + (u32)lr * 64 + swo;
                float x0 = acc[mi][ni][hh * 2], x1 = acc[mi][ni][hh * 2 + 1];
                __half h0, l0, h1, l1;
                split2(x0, h0, l0); split2(x1, h1, l1);
                __half2 hv = __halves2half2(h0, h1);
                __half2 lv = __halves2half2(l0, l1);
                asm volatile("st.shared.b32 [%0], %1;" :: "r"(saddr), "r"(*(u32*)&hv) : "memory");
                asm volatile("st.shared.b32 [%0], %1;" :: "r"(saddr + 8192), "r"(*(u32*)&lv) : "memory");
            }
    __syncthreads();
    if (tid == 0) {
        fence_async_shared();
        char* Cb = (char*)g_C + (size_t)b * (16 * 16384);
#pragma unroll
        for (int blk = 0; blk < 4; blk++) {
            int kc = (blk < 2) ? (2 * nb + blk) : (8 + 2 * nb + (blk - 2));
            cp_bulk_store(Cb + (size_t)kc * 16384, sb + blk * 16384, 16384);
        }
        bulk_store_commit();
        bulk_store_wait0();
    }
}

// ---------------------------------------------------------------------------
// k2 DUAL-GATE: z AND r for a 128x128 tile. 512 thr, 16 warps (4Mx4N, 32x32
// per gate). C staged ONCE per chunk. grid (2 nb, 512 rt). 1 CTA/SM.
// ---------------------------------------------------------------------------
__global__ __launch_bounds__(512, 1) void k2(const float* __restrict__ bias_z,
                                             const float* __restrict__ bias_r) {
    extern __shared__ char sm[];
    const int tid = threadIdx.x, lane = tid & 31, wid = tid >> 5;
    const int wm = wid >> 2, wn = wid & 3;
    const int nb = blockIdx.x, rt = blockIdx.y;

    const char* Cb = (const char*)g_C + (size_t)rt * (16 * 16384);
    const char* Bz = (const char*)g_Wz + (size_t)nb * (16 * 8192);
    const char* Br = (const char*)g_Wr + (size_t)nb * (16 * 8192);

    const u32 sb = smem_u32(sm);
    const u32 mb0 = sb + MB2;
    const u32 arow = (u32)(wm * 32 + (lane & 15)) * 64;
    const u32 aswp = ((((u32)lane & 15) >> 1) & 3) << 4;
    const u32 ahalf = (u32)(lane >> 4);
    const u32 bsl = bsl_of(lane);
    const u32 brow = (u32)(wn * 32 + bsl) * 64;
    const u32 bswp = ((bsl >> 1) & 3) << 4;
    const u32 bhalf = (u32)((lane >> 3) & 1);

    auto fill = [&](int j) {
        u32 st = sb + (j & 3) * STAGE2, mb = mb0 + (j & 3) * 8;
        mbar_expect(mb, STAGE2);
        cp_bulk(st,         Cb + (size_t)j * 16384, 16384, mb);
        cp_bulk(st + 16384, Bz + (size_t)j * 8192, 8192, mb);
        cp_bulk(st + 24576, Br + (size_t)j * 8192, 8192, mb);
    };

    if (tid == 0) {
#pragma unroll
        for (int s = 0; s < 4; s++) mbar_init(mb0 + s * 8, 1);
        fill(0); fill(1); fill(2);
    }
    __syncthreads();

    float accz[2][4][4], accr[2][4][4];
    ZERO_ACC(accz, 4); ZERO_ACC(accr, 4);

    for (int ch = 0; ch < 16; ch++) {
        const int s = ch & 3;
        mbar_wait(mb0 + s * 8, (ch >> 2) & 1);
        __syncthreads();
        if (tid == 0 && ch + 3 < 16) fill(ch + 3);
        const u32 sA = sb + s * STAGE2, sL = sA + 8192;
        const u32 sWz = sA + 16384, sWr = sA + 24576;
#pragma unroll
        for (int k16 = 0; k16 < 2; k16++) {
            const u32 goffA = (((2 * k16 + ahalf) << 4) ^ aswp);
            const u32 goffB = (((2 * k16 + bhalf) << 4) ^ bswp);
            u32 bfz[2][4], bfr[2][4];
#pragma unroll
            for (int q = 0; q < 2; q++) {
                ldsm4(bfz[q], sWz + brow + q * 1024 + goffB);
                ldsm4(bfr[q], sWr + brow + q * 1024 + goffB);
            }
            u32 ah[2][4], al[2][4];
#pragma unroll
            for (int mi = 0; mi < 2; mi++) {
                ldsm4(ah[mi], sA + arow + mi * 1024 + goffA);
                ldsm4(al[mi], sL + arow + mi * 1024 + goffA);
            }
#pragma unroll
            for (int mi = 0; mi < 2; mi++)
#pragma unroll
                for (int ni = 0; ni < 4; ni++) {
                    mma16816(accz[mi][ni], ah[mi], &bfz[ni >> 1][(ni & 1) * 2]);
                    mma16816(accr[mi][ni], ah[mi], &bfr[ni >> 1][(ni & 1) * 2]);
                }
#pragma unroll
            for (int mi = 0; mi < 2; mi++)
#pragma unroll
                for (int ni = 0; ni < 4; ni++) {
                    mma16816(accz[mi][ni], al[mi], &bfz[ni >> 1][(ni & 1) * 2]);
                    mma16816(accr[mi][ni], al[mi], &bfr[ni >> 1][(ni & 1) * 2]);
                }
        }
    }

    // epilogue: sigmoid -> SMEM (z at 0..64KB, r at 64..128KB) -> 2 bulk stores
    __syncthreads();
#pragma unroll
    for (int mi = 0; mi < 2; mi++)
#pragma unroll
        for (int ni = 0; ni < 4; ni++)
#pragma unroll
            for (int hh = 0; hh < 2; hh++) {
                int lr = wm * 32 + mi * 16 + (lane >> 2) + hh * 8;
                int cl = wn * 32 + ni * 8 + (lane & 3) * 2;
                float2 bbz = *(const float2*)(bias_z + (size_t)lr * 256 + nb * 128 + cl);
                float2 bbr = *(const float2*)(bias_r + (size_t)lr * 256 + nb * 128 + cl);
                float z0 = sigmoidf_fast(accz[mi][ni][hh * 2]     + bbz.x);
                float z1 = sigmoidf_fast(accz[mi][ni][hh * 2 + 1] + bbz.y);
                float r0 = sigmoidf_fast(accr[mi][ni][hh * 2]     + bbr.x);
                float r1 = sigmoidf_fast(accr[mi][ni][hh * 2 + 1] + bbr.y);
                u32 soff = (u32)lr * 512 + (((u32)cl * 4) ^ (((u32)lr & 3) << 5));
                asm volatile("st.shared.v2.f32 [%0], {%1, %2};"
                             :: "r"(sb + soff), "f"(z0), "f"(z1) : "memory");
                asm volatile("st.shared.v2.f32 [%0], {%1, %2};"
                             :: "r"(sb + 65536 + soff), "f"(r0), "f"(r1) : "memory");
            }
    __syncthreads();
    if (tid == 0) {
        fence_async_shared();
        size_t blk = (size_t)(rt * 2 + nb) * 16384;
        cp_bulk_store(g_Z + blk, sb, 65536);
        cp_bulk_store(g_R + blk, sb + 65536, 65536);
        bulk_store_commit();
        bulk_store_wait0();
    }
}

// ---------------------------------------------------------------------------
// k3 FULL-N: one CTA per rt covers all 256 cols. 512 thr, 16 warps (4Mx4N,
// warp 32x64). C staged ONCE. grid (512). 1 CTA/SM.
// ---------------------------------------------------------------------------
__global__ __launch_bounds__(512, 1) void k3(const float* __restrict__ bias_h,
                                             const float* __restrict__ hidden,
                                             float* __restrict__ Out) {
    extern __shared__ char sm[];
    const int tid = threadIdx.x, lane = tid & 31, wid = tid >> 5;
    const int wm = wid >> 2, wn = wid & 3;
    const int rt = blockIdx.x;

    const char* Cb = (const char*)g_C + (size_t)rt * (16 * 16384);
    const float* Zb = g_Z + (size_t)rt * 32768;   // two 16384-float blocks (nb0, nb1)
    const float* Rb = g_R + (size_t)rt * 32768;

    const u32 sb = smem_u32(sm);
    const u32 mb0 = sb + MB2;
    const u32 arow = (u32)(wm * 32 + (lane & 15)) * 64;
    const u32 aswp = ((((u32)lane & 15) >> 1) & 3) << 4;
    const u32 ahalf = (u32)(lane >> 4);
    const u32 bsl = bsl_of(lane);
    // warp covers cols wn*64..+64: W block nb = wn>>1, rows (wn&1)*64 + ...
    const u32 bblk = (u32)(wn >> 1) * 8192;
    const u32 brow = (u32)((wn & 1) * 64 + bsl) * 64;
    const u32 bswp = ((bsl >> 1) & 3) << 4;
    const u32 bhalf = (u32)((lane >> 3) & 1);

    // chunk j: j<8 -> C kc 8+j with Wh2 blk j ; j>=8 -> C kc j-8 with Wh1
    auto fill = [&](int j) {
        int kc = (j < 8) ? (8 + j) : (j - 8);
        const char* Wp = (j < 8) ? (const char*)g_Wh2 : (const char*)g_Wh1;
        int wi = (j < 8) ? j : (j - 8);
        u32 st = sb + (j & 3) * STAGE2, mb = mb0 + (j & 3) * 8;
        mbar_expect(mb, STAGE2);
        cp_bulk(st,         Cb + (size_t)kc * 16384, 16384, mb);
        cp_bulk(st + 16384, Wp + (size_t)wi * 8192, 8192, mb);
        cp_bulk(st + 24576, Wp + 65536 + (size_t)wi * 8192, 8192, mb);
    };

    if (tid == 0) {
#pragma unroll
        for (int s = 0; s < 4; s++) mbar_init(mb0 + s * 8, 1);
        fill(0); fill(1); fill(2);
    }
    __syncthreads();

    float acc[2][8][4];
    ZERO_ACC(acc, 8);

    for (int j = 0; j < 16; j++) {
        const int s = j & 3;
        mbar_wait(mb0 + s * 8, (j >> 2) & 1);
        __syncthreads();
        if (tid == 0 && j + 3 < 16) fill(j + 3);
        const u32 sA = sb + s * STAGE2, sL = sA + 8192;
        const u32 sB = sA + 16384 + bblk;
#pragma unroll
        for (int k16 = 0; k16 < 2; k16++) {
            const u32 goffA = (((2 * k16 + ahalf) << 4) ^ aswp);
            const u32 goffB = (((2 * k16 + bhalf) << 4) ^ bswp);
            u32 bf[4][4];
#pragma unroll
            for (int q = 0; q < 4; q++)
                ldsm4(bf[q], sB + brow + q * 1024 + goffB);
            u32 ah[2][4], al[2][4];
#pragma unroll
            for (int mi = 0; mi < 2; mi++) {
                ldsm4(ah[mi], sA + arow + mi * 1024 + goffA);
                ldsm4(al[mi], sL + arow + mi * 1024 + goffA);
            }
#pragma unroll
            for (int mi = 0; mi < 2; mi++)
#pragma unroll
                for (int ni = 0; ni < 8; ni++)
                    mma16816(acc[mi][ni], ah[mi], &bf[ni >> 1][(ni & 1) * 2]);
#pragma unroll
            for (int mi = 0; mi < 2; mi++)
#pragma unroll
                for (int ni = 0; ni < 8; ni++)
                    mma16816(acc[mi][ni], al[mi], &bf[ni >> 1][(ni & 1) * 2]);
        }
        if (j == 7) {
#pragma unroll
            for (int mi = 0; mi < 2; mi++)
#pragma unroll
                for (int ni = 0; ni < 8; ni++)
#pragma unroll
                    for (int hh = 0; hh < 2; hh++) {
                        int lr = wm * 32 + mi * 16 + (lane >> 2) + hh * 8;
                        int c  = wn * 64 + ni * 8 + (lane & 3) * 2;
                        int nb = c >> 7, cl = c & 127;
                        float2 rv = *(const float2*)(Rb + nb * 16384 + zr_off(lr, cl));
                        acc[mi][ni][hh * 2]     *= rv.x;
                        acc[mi][ni][hh * 2 + 1] *= rv.y;
                    }
        }
    }

#pragma unroll
    for (int mi = 0; mi < 2; mi++)
#pragma unroll
        for (int ni = 0; ni < 8; ni++)
#pragma unroll
            for (int hh = 0; hh < 2; hh++) {
                int lr = wm * 32 + mi * 16 + (lane >> 2) + hh * 8;
                int c  = wn * 64 + ni * 8 + (lane & 3) * 2;
                int nb = c >> 7, cl = c & 127;
                size_t off = ((size_t)rt * 128 + lr) * 256 + c;
                float2 zv = *(const float2*)(Zb + nb * 16384 + zr_off(lr, cl));
                float2 hv = *(const float2*)(hidden + off);
                float2 bv = *(const float2*)(bias_h + (size_t)lr * 256 + c);
                float t0 = tanhf(acc[mi][ni][hh * 2]     + bv.x);
                float t1 = tanhf(acc[mi][ni][hh * 2 + 1] + bv.y);
                float2 o;
                o.x = zv.x * hv.x + (1.0f - zv.x) * t0;
                o.y = zv.y * hv.y + (1.0f - zv.y) * t1;
                *(float2*)(Out + off) = o;
            }
}

// ---------------------------------------------------------------------------
extern "C" void kernel_launch(void* const* d_in, const int* in_sizes, int n_in,
                              void* d_out, int out_size) {
    (void)in_sizes; (void)n_in; (void)out_size;
    const float* X      = (const float*)d_in[0];
    const float* A      = (const float*)d_in[1];
    const float* hidden = (const float*)d_in[2];
    const float* Wz1    = (const float*)d_in[3];
    const float* Wz2    = (const float*)d_in[4];
    const float* Wr1    = (const float*)d_in[5];
    const float* Wr2    = (const float*)d_in[6];
    const float* Wh1    = (const float*)d_in[7];
    const float* Wh2    = (const float*)d_in[8];
    const float* bz     = (const float*)d_in[9];
    const float* br     = (const float*)d_in[10];
    const float* bh     = (const float*)d_in[11];
    float* out          = (float*)d_out;

    static bool attr_done = false;
    if (!attr_done) {
        cudaFuncSetAttribute(k1, cudaFuncAttributeMaxDynamicSharedMemorySize, KSMEM1);
        cudaFuncSetAttribute(k2, cudaFuncAttributeMaxDynamicSharedMemorySize, KSMEM2);
        cudaFuncSetAttribute(k3, cudaFuncAttributeMaxDynamicSharedMemorySize, KSMEM2);
        attr_done = true;
    }

    conv_A<<<8192, 256>>>(A);
    conv_XH<<<dim3(8, 4, 1024), 256>>>(X, hidden);
    conv_W<<<dim3(8, 8, 6), 256>>>(Wz1, Wz2, Wr1, Wr2, Wh1, Wh2);

    k1<<<dim3(4, 512), 256, KSMEM1>>>();
    k2<<<dim3(2, 512), 512, KSMEM2>>>(bz, br);
    k3<<<512, 512, KSMEM2>>>(bh, hidden, out);
}

// round 17
// speedup vs baseline: 1.1754x; 1.1754x over previous
#include <cuda_runtime.h>
#include <cuda_fp16.h>

typedef unsigned int u32;

#define B_    512
#define ROWS  65536   // B_*128

// ---------------------------------------------------------------------------
// Device-global scratch (allocation-free rule)
// HL block = 16KB: [hi: 128 row x 32 k][lo: 128 row x 32 k], swizzled:
//   byte_in_half_block = row*64 + ((col*2) ^ (((row>>1)&3)<<4))
// g_A  : [b][kc:4]  HL blocks
// g_C  : [rt][kc:16] HL blocks
// g_Xt/g_Ht : [b][kc:4][256 feat][32 tok] fp16 blocks (8KB)
// g_Wz/g_Wr : [nb:2][kc:16][128 n][32 k] 8KB blocks
// g_Wh1/g_Wh2 : [nb:2][kc:8][128 n][32 k] 8KB blocks
// ---------------------------------------------------------------------------
__device__ __align__(128) __half g_A[(size_t)B_ * 4 * 8192];
__device__ __align__(128) __half g_Xt[(size_t)B_ * 256 * 128];
__device__ __align__(128) __half g_Ht[(size_t)B_ * 256 * 128];
__device__ __align__(128) __half g_C[(size_t)ROWS * 1024];      // 134MB (hi+lo)
__device__ float  g_Z[(size_t)ROWS * 256];
__device__ float  g_R[(size_t)ROWS * 256];
__device__ __align__(128) __half g_Wz[256 * 512];
__device__ __align__(128) __half g_Wr[256 * 512];
__device__ __align__(128) __half g_Wh1[256 * 256];
__device__ __align__(128) __half g_Wh2[256 * 256];

// ---------------------------------------------------------------------------
// Helpers
// ---------------------------------------------------------------------------
__device__ __forceinline__ u32 smem_u32(const void* p) {
    u32 a;
    asm("{ .reg .u64 t; cvta.to.shared.u64 t, %1; cvt.u32.u64 %0, t; }" : "=r"(a) : "l"(p));
    return a;
}
__device__ __forceinline__ void ldsm4(u32* r, u32 addr) {
    asm volatile("ldmatrix.sync.aligned.m8n8.x4.shared.b16 {%0,%1,%2,%3}, [%4];"
                 : "=r"(r[0]), "=r"(r[1]), "=r"(r[2]), "=r"(r[3]) : "r"(addr));
}
__device__ __forceinline__ void mma16816(float* d, const u32* a, const u32* b) {
    asm volatile(
        "mma.sync.aligned.m16n8k16.row.col.f32.f16.f16.f32 "
        "{%0,%1,%2,%3}, {%4,%5,%6,%7}, {%8,%9}, {%0,%1,%2,%3};"
        : "+f"(d[0]), "+f"(d[1]), "+f"(d[2]), "+f"(d[3])
        : "r"(a[0]), "r"(a[1]), "r"(a[2]), "r"(a[3]), "r"(b[0]), "r"(b[1]));
}
__device__ __forceinline__ float sigmoidf_fast(float x) {
    return 1.0f / (1.0f + __expf(-x));
}
__device__ __forceinline__ void split2(float x, __half& h, __half& l) {
    h = __float2half_rn(x);
    l = __float2half_rn(x - __half2float(h));
}
// ---- bulk DMA + mbarrier ----
__device__ __forceinline__ void cp_bulk(u32 sdst, const void* gsrc, u32 bytes, u32 mbar) {
    asm volatile(
        "{ .reg .u64 p; cvta.to.global.u64 p, %1;\n\t"
        "cp.async.bulk.shared::cluster.global.mbarrier::complete_tx::bytes [%0], [p], %2, [%3]; }"
        :: "r"(sdst), "l"(gsrc), "r"(bytes), "r"(mbar) : "memory");
}
__device__ __forceinline__ void cp_bulk_store(void* gdst, u32 ssrc, u32 bytes) {
    asm volatile(
        "{ .reg .u64 p; cvta.to.global.u64 p, %0;\n\t"
        "cp.async.bulk.global.shared::cta.bulk_group [p], [%1], %2; }"
        :: "l"(gdst), "r"(ssrc), "r"(bytes) : "memory");
}
__device__ __forceinline__ void bulk_store_commit() {
    asm volatile("cp.async.bulk.commit_group;" ::: "memory");
}
__device__ __forceinline__ void bulk_store_wait0() {
    asm volatile("cp.async.bulk.wait_group 0;" ::: "memory");
}
__device__ __forceinline__ void fence_async_shared() {
    asm volatile("fence.proxy.async.shared::cta;" ::: "memory");
}
__device__ __forceinline__ void mbar_init(u32 addr, u32 cnt) {
    asm volatile("mbarrier.init.shared.b64 [%0], %1;" :: "r"(addr), "r"(cnt) : "memory");
}
__device__ __forceinline__ void mbar_expect(u32 addr, u32 bytes) {
    asm volatile("mbarrier.arrive.expect_tx.shared::cta.b64 _, [%0], %1;"
                 :: "r"(addr), "r"(bytes) : "memory");
}
__device__ __forceinline__ void mbar_wait(u32 addr, u32 parity) {
    asm volatile(
        "{\n\t.reg .pred P;\n\t"
        "WAIT_%=:\n\t"
        "mbarrier.try_wait.parity.acquire.cta.shared::cta.b64 P, [%0], %1, 0x989680;\n\t"
        "@!P bra.uni WAIT_%=;\n\t}"
        :: "r"(addr), "r"(parity) : "memory");
}

#define ZERO_ACC8(acc) \
    _Pragma("unroll") for (int _a = 0; _a < 2; _a++) \
    _Pragma("unroll") for (int _c = 0; _c < 8; _c++) \
    _Pragma("unroll") for (int _d = 0; _d < 4; _d++) acc[_a][_c][_d] = 0.0f;

// ---------------------------------------------------------------------------
// Fused conversion kernel: zones [0,8192) conv_A, [8192,40960) conv_XH,
// [40960,41344) conv_W. 256 threads everywhere; identical per-element math.
// ---------------------------------------------------------------------------
__global__ __launch_bounds__(256) void conv_all(
    const float* __restrict__ A, const float* __restrict__ X,
    const float* __restrict__ Hd,
    const float* __restrict__ Wz1, const float* __restrict__ Wz2,
    const float* __restrict__ Wr1, const float* __restrict__ Wr2,
    const float* __restrict__ Wh1, const float* __restrict__ Wh2)
{
    __shared__ float s[32][33];
    const int bid = blockIdx.x;

    if (bid < 8192) {
        // ---- conv_A ----
        size_t i = ((size_t)bid * 256 + threadIdx.x) * 4;
        float4 v = *(const float4*)(A + i);
        int b   = (int)(i >> 14);
        int rem = (int)(i & 16383);
        int row = rem >> 7, col = rem & 127;
        int kc = col >> 5, kk = col & 31;
        __half h0, h1, h2, h3, l0, l1, l2, l3;
        split2(v.x, h0, l0); split2(v.y, h1, l1); split2(v.z, h2, l2); split2(v.w, h3, l3);
        u32 swo = (u32)((kk * 2) ^ (((row >> 1) & 3) << 4));
        size_t hidx = (size_t)(b * 4 + kc) * 8192 + (size_t)row * 32 + (swo >> 1);
        *(__half2*)(g_A + hidx)            = __halves2half2(h0, h1);
        *(__half2*)(g_A + hidx + 2)        = __halves2half2(h2, h3);
        *(__half2*)(g_A + hidx + 4096)     = __halves2half2(l0, l1);
        *(__half2*)(g_A + hidx + 4096 + 2) = __halves2half2(l2, l3);
    } else if (bid < 40960) {
        // ---- conv_XH : idx = z*32 + ty4*8 + fx  (orig grid (8,4,1024)) ----
        int idx = bid - 8192;
        int z  = idx >> 5;
        int yy = (idx >> 3) & 3;
        int xx = idx & 7;
        int b = z & (B_ - 1);
        const float* src = (z < B_) ? X : Hd;
        __half* dst = (z < B_) ? g_Xt : g_Ht;
        int tx = threadIdx.x & 31, ty = threadIdx.x >> 5;
        int f0 = xx * 32, t0 = yy * 32;
        const float* sp = src + (size_t)b * 128 * 256;
#pragma unroll
        for (int r = 0; r < 4; r++)
            s[ty + 8 * r][tx] = sp[(size_t)(t0 + ty + 8 * r) * 256 + f0 + tx];
        __syncthreads();
#pragma unroll
        for (int r = 0; r < 4; r++) {
            int feat = f0 + ty + 8 * r;
            int tok  = t0 + tx;
            int kc = tok >> 5, tk = tok & 31;
            u32 swo = (u32)((tk * 2) ^ (((feat >> 1) & 3) << 4));
            size_t di = ((size_t)(b * 4 + kc) * 256 + feat) * 32 + (swo >> 1);
            dst[di] = __float2half_rn(s[tx][ty + 8 * r]);
        }
    } else {
        // ---- conv_W : idx = job*64 + ky*8 + kx  (orig grid (8,8,6)) ----
        int idx = bid - 40960;
        int job = idx >> 6;
        int ky  = (idx >> 3) & 7;
        int kx  = idx & 7;
        const float* src; __half* dst; int koff, kcn;
        switch (job) {
            case 0:  src = Wz1; dst = g_Wz;  koff = 0;   kcn = 16; break;
            case 1:  src = Wz2; dst = g_Wz;  koff = 256; kcn = 16; break;
            case 2:  src = Wr1; dst = g_Wr;  koff = 0;   kcn = 16; break;
            case 3:  src = Wr2; dst = g_Wr;  koff = 256; kcn = 16; break;
            case 4:  src = Wh1; dst = g_Wh1; koff = 0;   kcn = 8;  break;
            default: src = Wh2; dst = g_Wh2; koff = 0;   kcn = 8;  break;
        }
        int tx = threadIdx.x & 31, ty = threadIdx.x >> 5;
        int n0 = kx * 32, k0 = ky * 32;
#pragma unroll
        for (int r = 0; r < 4; r++)
            s[ty + 8 * r][tx] = src[(size_t)(k0 + ty + 8 * r) * 256 + n0 + tx];
        __syncthreads();
#pragma unroll
        for (int r = 0; r < 4; r++) {
            int n = n0 + ty + 8 * r;
            int k = koff + k0 + tx;
            int nb = n >> 7, nr = n & 127, kc = k >> 5, kk = k & 31;
            size_t hidx = (size_t)(nb * kcn + kc) * 4096 + nr * 32
                        + ((((kk * 2) ^ (((nr >> 1) & 3) << 4))) >> 1);
            dst[hidx] = __float2half_rn(s[tx][ty + 8 * r]);
        }
    }
}

// ---------------------------------------------------------------------------
// Shared MMA inner step on one stage (blocked swizzle addressing).
// ---------------------------------------------------------------------------
struct LaneCtx {
    u32 arow, aswp, ahalf, brow, bswp, bhalf;
};
__device__ __forceinline__ void mma_stage(float acc[2][8][4], u32 sA, u32 sL, u32 sB,
                                          const LaneCtx& lc) {
#pragma unroll
    for (int k16 = 0; k16 < 2; k16++) {
        const u32 goffA = (((2 * k16 + lc.ahalf) << 4) ^ lc.aswp);
        const u32 goffB = (((2 * k16 + lc.bhalf) << 4) ^ lc.bswp);
        u32 bf[4][4];
#pragma unroll
        for (int q = 0; q < 4; q++)
            ldsm4(bf[q], sB + lc.brow + q * 1024 + goffB);
        u32 ah[2][4], al[2][4];
#pragma unroll
        for (int mi = 0; mi < 2; mi++) {
            ldsm4(ah[mi], sA + lc.arow + mi * 1024 + goffA);
            ldsm4(al[mi], sL + lc.arow + mi * 1024 + goffA);
        }
#pragma unroll
        for (int mi = 0; mi < 2; mi++)
#pragma unroll
            for (int ni = 0; ni < 8; ni++)
                mma16816(acc[mi][ni], ah[mi], &bf[ni >> 1][(ni & 1) * 2]);
#pragma unroll
        for (int mi = 0; mi < 2; mi++)
#pragma unroll
            for (int ni = 0; ni < 8; ni++)
                mma16816(acc[mi][ni], al[mi], &bf[ni >> 1][(ni & 1) * 2]);
    }
}
__device__ __forceinline__ LaneCtx make_ctx(int wm, int wn, int lane) {
    LaneCtx lc;
    lc.arow  = (u32)(wm * 32 + (lane & 15)) * 64;
    lc.aswp  = ((((u32)lane & 15) >> 1) & 3) << 4;
    lc.ahalf = (u32)(lane >> 4);
    u32 bsl  = (u32)((lane & 7) + ((lane >> 4) << 3));
    lc.brow  = (u32)(wn * 64 + bsl) * 64;
    lc.bswp  = ((bsl >> 1) & 3) << 4;
    lc.bhalf = (u32)((lane >> 3) & 1);
    return lc;
}

#define STAGE 24576
#define MBOFF 98304
#define KSMEM (98304 + 64)

// ---------------------------------------------------------------------------
// k1: per (nb, b): C[128 tok, 128 cols] (X feats nb*64.. | H feats nb*64..).
// ALL-BULK loads, SMEM-repack + BULK STORES epilogue. grid (4, 512).
// ---------------------------------------------------------------------------
__global__ __launch_bounds__(256, 2) void k1() {
    extern __shared__ char sm[];
    const int tid = threadIdx.x, lane = tid & 31, wid = tid >> 5;
    const int wm = wid >> 1, wn = wid & 1;
    const int nb = blockIdx.x, b = blockIdx.y;

    const char* Ab = (const char*)g_A + (size_t)b * (4 * 16384);
    const char* Bx = (const char*)g_Xt + (size_t)b * 65536 + (size_t)nb * 4096;
    const char* Bh = (const char*)g_Ht + (size_t)b * 65536 + (size_t)nb * 4096;

    const u32 sb = smem_u32(sm);
    const u32 mb0 = sb + MBOFF;
    const LaneCtx lc = make_ctx(wm, wn, lane);

    if (tid == 0) {
#pragma unroll
        for (int s = 0; s < 4; s++) mbar_init(mb0 + s * 8, 1);
#pragma unroll
        for (int j = 0; j < 4; j++) {
            u32 st = sb + j * STAGE, mb = mb0 + j * 8;
            mbar_expect(mb, STAGE);
            cp_bulk(st,                Ab + (size_t)j * 16384, 16384, mb);
            cp_bulk(st + 16384,        Bx + (size_t)j * 16384, 4096, mb);
            cp_bulk(st + 16384 + 4096, Bh + (size_t)j * 16384, 4096, mb);
        }
    }
    __syncthreads();

    float acc[2][8][4];
    ZERO_ACC8(acc);

    for (int ch = 0; ch < 4; ch++) {
        mbar_wait(mb0 + ch * 8, 0);
        __syncthreads();
        const u32 sA = sb + ch * STAGE;
        mma_stage(acc, sA, sA + 8192, sA + 16384, lc);
    }

    __syncthreads();
#pragma unroll
    for (int mi = 0; mi < 2; mi++)
#pragma unroll
        for (int ni = 0; ni < 8; ni++)
#pragma unroll
            for (int hh = 0; hh < 2; hh++) {
                int lr = wm * 32 + mi * 16 + (lane >> 2) + hh * 8;
                int cl = wn * 64 + ni * 8 + (lane & 3) * 2;
                int blk = cl >> 5, cc = cl & 31;
                u32 swo = (u32)((cc * 2) ^ (((lr >> 1) & 3) << 4));
                u32 saddr = sb + blk * 16384 + (u32)lr * 64 + swo;
                float x0 = acc[mi][ni][hh * 2], x1 = acc[mi][ni][hh * 2 + 1];
                __half h0, l0, h1, l1;
                split2(x0, h0, l0); split2(x1, h1, l1);
                __half2 hv = __halves2half2(h0, h1);
                __half2 lv = __halves2half2(l0, l1);
                asm volatile("st.shared.b32 [%0], %1;" :: "r"(saddr), "r"(*(u32*)&hv) : "memory");
                asm volatile("st.shared.b32 [%0], %1;" :: "r"(saddr + 8192), "r"(*(u32*)&lv) : "memory");
            }
    __syncthreads();
    if (tid == 0) {
        fence_async_shared();
        char* Cb = (char*)g_C + (size_t)b * (16 * 16384);
#pragma unroll
        for (int blk = 0; blk < 4; blk++) {
            int kc = (blk < 2) ? (2 * nb + blk) : (8 + 2 * nb + (blk - 2));
            cp_bulk_store(Cb + (size_t)kc * 16384, sb + blk * 16384, 16384);
        }
        bulk_store_commit();
        bulk_store_wait0();
    }
}

// ---------------------------------------------------------------------------
// k2: Z/R = sigmoid(C @ W^T + bias), K=512 (16 chunks), N=128 per CTA.
// grid (4, 512): x = gate*2 + nb. 2 bulks/chunk.
// ---------------------------------------------------------------------------
__global__ __launch_bounds__(256, 2) void k2(const float* __restrict__ bias_z,
                                             const float* __restrict__ bias_r) {
    extern __shared__ char sm[];
    const int tid = threadIdx.x, lane = tid & 31, wid = tid >> 5;
    const int wm = wid >> 1, wn = wid & 1;
    const int gate = blockIdx.x >> 1, nb = blockIdx.x & 1, rt = blockIdx.y;

    const char* Cb = (const char*)g_C + (size_t)rt * (16 * 16384);
    const char* Bb = (const char*)(gate ? g_Wr : g_Wz) + (size_t)nb * (16 * 8192);

    const u32 sb = smem_u32(sm);
    const u32 mb0 = sb + MBOFF;
    const LaneCtx lc = make_ctx(wm, wn, lane);

    if (tid == 0) {
#pragma unroll
        for (int s = 0; s < 4; s++) mbar_init(mb0 + s * 8, 1);
        for (int j = 0; j < 3; j++) {
            u32 st = sb + j * STAGE, mb = mb0 + j * 8;
            mbar_expect(mb, STAGE);
            cp_bulk(st,         Cb + (size_t)j * 16384, 16384, mb);
            cp_bulk(st + 16384, Bb + (size_t)j * 8192, 8192, mb);
        }
    }
    __syncthreads();

    float acc[2][8][4];
    ZERO_ACC8(acc);

    for (int ch = 0; ch < 16; ch++) {
        const int s = ch & 3;
        mbar_wait(mb0 + s * 8, (ch >> 2) & 1);
        __syncthreads();
        if (tid == 0 && ch + 3 < 16) {
            int j = ch + 3;
            u32 st = sb + (j & 3) * STAGE, mb = mb0 + (j & 3) * 8;
            mbar_expect(mb, STAGE);
            cp_bulk(st,         Cb + (size_t)j * 16384, 16384, mb);
            cp_bulk(st + 16384, Bb + (size_t)j * 8192, 8192, mb);
        }
        const u32 sA = sb + s * STAGE;
        mma_stage(acc, sA, sA + 8192, sA + 16384, lc);
    }

    float* out = gate ? g_R : g_Z;
    const float* bias = gate ? bias_r : bias_z;
#pragma unroll
    for (int mi = 0; mi < 2; mi++)
#pragma unroll
        for (int ni = 0; ni < 8; ni++)
#pragma unroll
            for (int hh = 0; hh < 2; hh++) {
                int lr = wm * 32 + mi * 16 + (lane >> 2) + hh * 8;
                int c  = nb * 128 + wn * 64 + ni * 8 + (lane & 3) * 2;
                float2 bb = *(const float2*)(bias + (size_t)lr * 256 + c);
                float2 o;
                o.x = sigmoidf_fast(acc[mi][ni][hh * 2]     + bb.x);
                o.y = sigmoidf_fast(acc[mi][ni][hh * 2 + 1] + bb.y);
                *(float2*)(out + ((size_t)rt * 128 + lr) * 256 + c) = o;
            }
}

// ---------------------------------------------------------------------------
// k3: acc = AH@Wh2 (8) ; acc *= r ; acc += AX@Wh1 (8) ; GRU epilogue.
// ALL-BULK. grid (2 nb, 512 rt).
// ---------------------------------------------------------------------------
__global__ __launch_bounds__(256, 2) void k3(const float* __restrict__ bias_h,
                                             const float* __restrict__ hidden,
                                             float* __restrict__ Out) {
    extern __shared__ char sm[];
    const int tid = threadIdx.x, lane = tid & 31, wid = tid >> 5;
    const int wm = wid >> 1, wn = wid & 1;
    const int nb = blockIdx.x, rt = blockIdx.y;

    const char* Cb = (const char*)g_C + (size_t)rt * (16 * 16384);
    const char* W2 = (const char*)g_Wh2 + (size_t)nb * (8 * 8192);
    const char* W1 = (const char*)g_Wh1 + (size_t)nb * (8 * 8192);

    const u32 sb = smem_u32(sm);
    const u32 mb0 = sb + MBOFF;
    const LaneCtx lc = make_ctx(wm, wn, lane);

    auto fill = [&](int j) {
        int kc = (j < 8) ? (8 + j) : (j - 8);
        const char* Wp = (j < 8) ? (W2 + (size_t)j * 8192) : (W1 + (size_t)(j - 8) * 8192);
        u32 st = sb + (j & 3) * STAGE, mb = mb0 + (j & 3) * 8;
        mbar_expect(mb, STAGE);
        cp_bulk(st,         Cb + (size_t)kc * 16384, 16384, mb);
        cp_bulk(st + 16384, Wp, 8192, mb);
    };

    if (tid == 0) {
#pragma unroll
        for (int s = 0; s < 4; s++) mbar_init(mb0 + s * 8, 1);
        fill(0); fill(1); fill(2);
    }
    __syncthreads();

    float acc[2][8][4];
    ZERO_ACC8(acc);

    for (int j = 0; j < 16; j++) {
        const int s = j & 3;
        mbar_wait(mb0 + s * 8, (j >> 2) & 1);
        __syncthreads();
        if (tid == 0 && j + 3 < 16) fill(j + 3);
        const u32 sA = sb + s * STAGE;
        mma_stage(acc, sA, sA + 8192, sA + 16384, lc);
        if (j == 7) {
#pragma unroll
            for (int mi = 0; mi < 2; mi++)
#pragma unroll
                for (int ni = 0; ni < 8; ni++)
#pragma unroll
                    for (int hh = 0; hh < 2; hh++) {
                        int lr = wm * 32 + mi * 16 + (lane >> 2) + hh * 8;
                        int c  = nb * 128 + wn * 64 + ni * 8 + (lane & 3) * 2;
                        float2 rv = *(const float2*)(g_R + ((size_t)rt * 128 + lr) * 256 + c);
                        acc[mi][ni][hh * 2]     *= rv.x;
                        acc[mi][ni][hh * 2 + 1] *= rv.y;
                    }
        }
    }

#pragma unroll
    for (int mi = 0; mi < 2; mi++)
#pragma unroll
        for (int ni = 0; ni < 8; ni++)
#pragma unroll
            for (int hh = 0; hh < 2; hh++) {
                int lr = wm * 32 + mi * 16 + (lane >> 2) + hh * 8;
                int c  = nb * 128 + wn * 64 + ni * 8 + (lane & 3) * 2;
                size_t off = ((size_t)rt * 128 + lr) * 256 + c;
                float2 zv = *(const float2*)(g_Z + off);
                float2 hv = *(const float2*)(hidden + off);
                float2 bv = *(const float2*)(bias_h + (size_t)lr * 256 + c);
                float t0 = tanhf(acc[mi][ni][hh * 2]     + bv.x);
                float t1 = tanhf(acc[mi][ni][hh * 2 + 1] + bv.y);
                float2 o;
                o.x = zv.x * hv.x + (1.0f - zv.x) * t0;
                o.y = zv.y * hv.y + (1.0f - zv.y) * t1;
                *(float2*)(Out + off) = o;
            }
}

// ---------------------------------------------------------------------------
extern "C" void kernel_launch(void* const* d_in, const int* in_sizes, int n_in,
                              void* d_out, int out_size) {
    (void)in_sizes; (void)n_in; (void)out_size;
    const float* X      = (const float*)d_in[0];
    const float* A      = (const float*)d_in[1];
    const float* hidden = (const float*)d_in[2];
    const float* Wz1    = (const float*)d_in[3];
    const float* Wz2    = (const float*)d_in[4];
    const float* Wr1    = (const float*)d_in[5];
    const float* Wr2    = (const float*)d_in[6];
    const float* Wh1    = (const float*)d_in[7];
    const float* Wh2    = (const float*)d_in[8];
    const float* bz     = (const float*)d_in[9];
    const float* br     = (const float*)d_in[10];
    const float* bh     = (const float*)d_in[11];
    float* out          = (float*)d_out;

    static bool attr_done = false;
    if (!attr_done) {
        cudaFuncSetAttribute(k1, cudaFuncAttributeMaxDynamicSharedMemorySize, KSMEM);
        cudaFuncSetAttribute(k2, cudaFuncAttributeMaxDynamicSharedMemorySize, KSMEM);
        cudaFuncSetAttribute(k3, cudaFuncAttributeMaxDynamicSharedMemorySize, KSMEM);
        attr_done = true;
    }

    conv_all<<<41344, 256>>>(A, X, hidden, Wz1, Wz2, Wr1, Wr2, Wh1, Wh2);

    k1<<<dim3(4, 512), 256, KSMEM>>>();
    k2<<<dim3(4, 512), 256, KSMEM>>>(bz, br);
    k3<<<dim3(2, 512), 256, KSMEM>>>(bh, hidden, out);
}